// round 5
// baseline (speedup 1.0000x reference)
#include <cuda_runtime.h>
#include <cuda_fp16.h>

// Problem constants (fixed by the reference: B=2, C=8, L=256, D=128)
#define B_  2
#define C_  8
#define L_  256
#define D_  128
#define TI  32           // output tile rows per block
#define TJ  32           // output tile cols per block
#define THREADS 128      // 16 (ti) x 8 (tj); each thread: 2 rows x 4 cols

__device__ __forceinline__ __half2 tanh_h2(__half2 x) {
    unsigned xi = *reinterpret_cast<unsigned*>(&x);
    unsigned yi;
    asm("tanh.approx.f16x2 %0, %1;" : "=r"(yi) : "r"(xi));
    return *reinterpret_cast<__half2*>(&yi);
}

struct alignas(8) h2x2 { __half2 a, b; };

// smem: s/e stored fp16, d-major [d][row]  (8 KB each), v fp32 (512 B)
__global__ __launch_bounds__(THREADS)
void Add_Attn_Layer_59055800320841_kernel(const float* __restrict__ S,
                                          const float* __restrict__ E,
                                          const float* __restrict__ V,
                                          float* __restrict__ out) {
    __shared__ __half sH[D_ * TI];
    __shared__ __half eH[D_ * TJ];
    __shared__ float  vv[D_];

    const int bc = blockIdx.z;            // b*C + c   (0..15)
    const int i0 = blockIdx.y * TI;
    const int j0 = blockIdx.x * TJ;

    const float* Sbase = S + (size_t)bc * L_ * D_ + (size_t)i0 * D_;
    const float* Ebase = E + (size_t)bc * L_ * D_ + (size_t)j0 * D_;

    const int tid = threadIdx.x;

    vv[tid] = V[tid];                      // THREADS == D_

    // Load + transpose + fp32->fp16 convert: gmem [row][d] -> smem [d][row].
    // Lanes take consecutive rows at the same d4 -> coalesced 16B gmem loads;
    // smem 2B stores within a warp are contiguous 64B per d -> conflict-free.
    #pragma unroll
    for (int idx = tid; idx < TI * (D_ / 4); idx += THREADS) {
        const int row = idx & (TI - 1);
        const int d4  = idx >> 5;          // TI == 32
        const float4 sv = *reinterpret_cast<const float4*>(Sbase + row * D_ + d4 * 4);
        const float4 ev = *reinterpret_cast<const float4*>(Ebase + row * D_ + d4 * 4);
        sH[(4 * d4 + 0) * TI + row] = __float2half_rn(sv.x);
        sH[(4 * d4 + 1) * TI + row] = __float2half_rn(sv.y);
        sH[(4 * d4 + 2) * TI + row] = __float2half_rn(sv.z);
        sH[(4 * d4 + 3) * TI + row] = __float2half_rn(sv.w);
        eH[(4 * d4 + 0) * TI + row] = __float2half_rn(ev.x);
        eH[(4 * d4 + 1) * TI + row] = __float2half_rn(ev.y);
        eH[(4 * d4 + 2) * TI + row] = __float2half_rn(ev.z);
        eH[(4 * d4 + 3) * TI + row] = __float2half_rn(ev.w);
    }
    __syncthreads();

    // Thread -> 2 rows x 4 cols
    const int tj = tid & 7;
    const int ti = tid >> 3;
    const int il = 2 * ti;
    const int jl = 4 * tj;

    float a00 = 0.f, a01 = 0.f, a02 = 0.f, a03 = 0.f;
    float a10 = 0.f, a11 = 0.f, a12 = 0.f, a13 = 0.f;

    const __half2* sp2 = reinterpret_cast<const __half2*>(sH);  // [d*16 + ti]
    const h2x2*    ep2 = reinterpret_cast<const h2x2*>(eH);     // [d*8  + tj]

    #pragma unroll
    for (int d0 = 0; d0 < D_; d0 += 4) {
        const float4 v4 = *reinterpret_cast<const float4*>(vv + d0);
        #pragma unroll
        for (int q = 0; q < 4; q++) {
            const int d = d0 + q;
            const float vd = (q == 0) ? v4.x : (q == 1) ? v4.y : (q == 2) ? v4.z : v4.w;
            const __half2 s2 = sp2[d * (TI / 2) + ti];     // (s_il, s_il+1)
            const h2x2    e2 = ep2[d * (TJ / 4) + tj];     // (e_jl..e_jl+3)
            const __half2 slo = __low2half2(s2);           // folded into HADD2 sel
            const __half2 shi = __high2half2(s2);

            const __half2 t0 = tanh_h2(__hadd2(slo, e2.a)); // row0, cols 0,1
            const __half2 t1 = tanh_h2(__hadd2(slo, e2.b)); // row0, cols 2,3
            const __half2 t2 = tanh_h2(__hadd2(shi, e2.a)); // row1, cols 0,1
            const __half2 t3 = tanh_h2(__hadd2(shi, e2.b)); // row1, cols 2,3

            const float2 f0 = __half22float2(t0);
            const float2 f1 = __half22float2(t1);
            const float2 f2 = __half22float2(t2);
            const float2 f3 = __half22float2(t3);

            a00 = fmaf(vd, f0.x, a00);  a01 = fmaf(vd, f0.y, a01);
            a02 = fmaf(vd, f1.x, a02);  a03 = fmaf(vd, f1.y, a03);
            a10 = fmaf(vd, f2.x, a10);  a11 = fmaf(vd, f2.y, a11);
            a12 = fmaf(vd, f3.x, a12);  a13 = fmaf(vd, f3.y, a13);
        }
    }

    // out[b][i][j][c], c fastest; bc = b*C + c
    const int b = bc >> 3;
    const int c = bc & 7;
    const int i = i0 + il;
    const int j = j0 + jl;
    float* o = out + (((size_t)b * L_ + i) * L_ + j) * C_ + c;
    const size_t row_stride = (size_t)L_ * C_;   // i -> i+1
    o[0 * C_]              = a00;
    o[1 * C_]              = a01;
    o[2 * C_]              = a02;
    o[3 * C_]              = a03;
    o[row_stride + 0 * C_] = a10;
    o[row_stride + 1 * C_] = a11;
    o[row_stride + 2 * C_] = a12;
    o[row_stride + 3 * C_] = a13;
}

extern "C" void kernel_launch(void* const* d_in, const int* in_sizes, int n_in,
                              void* d_out, int out_size) {
    (void)in_sizes; (void)n_in; (void)out_size;
    const float* S = (const float*)d_in[0];   // start_hidden [B,C,L,D]
    const float* E = (const float*)d_in[1];   // end_hidden   [B,C,L,D]
    const float* V = (const float*)d_in[2];   // v [D]
    float* out = (float*)d_out;               // [B,L,L,C] float32

    dim3 grid(L_ / TJ, L_ / TI, B_ * C_);     // (8, 8, 16) = 1024 blocks
    Add_Attn_Layer_59055800320841_kernel<<<grid, THREADS>>>(S, E, V, out);
}